// round 2
// baseline (speedup 1.0000x reference)
#include <cuda_runtime.h>
#include <math.h>

// Problem dims (fixed)
#define MDIM 32768   // B*T
#define NDIM 1024    // H
#define KDIM 1024    // H
#define BSZ  8
#define TSZ  4096
#define SSZ  16

// ---------------- scratch (device globals; no allocation allowed) ----------
__device__ float g_xp[(size_t)MDIM * NDIM];   // x @ W_in + b_in
__device__ float g_y [(size_t)MDIM * NDIM];   // tanh(...)
__device__ float g_WG[1024 * 48];             // [WBB | W_ig | W_fg] folded
__device__ float g_gb[48];                    // [bBB | b_ig | b_fg]
__device__ float g_a [BSZ * SSZ * TSZ];       // fg  (chain-major [B,S,T])
__device__ float g_bq[BSZ * SSZ * TSZ];       // ig*Bx
__device__ float g_h [(size_t)MDIM * SSZ];    // hs row-major [M,16]

// ---------------- fold: WBB = W_B @ B_mat, plus gate weight/bias packing ---
__global__ void fold_kernel(const float* __restrict__ W_B,
                            const float* __restrict__ B_mat,
                            const float* __restrict__ b_B,
                            const float* __restrict__ W_ig,
                            const float* __restrict__ b_ig,
                            const float* __restrict__ W_fg,
                            const float* __restrict__ b_fg)
{
    __shared__ float red[128][17];
    const int tid = threadIdx.x;
    const int i = blockIdx.x;              // 0..1023 = WG rows; 1024 = bias row
    const float* rowp = (i < 1024) ? (W_B + (size_t)i * 1024) : b_B;

    float acc[16];
#pragma unroll
    for (int s = 0; s < 16; s++) acc[s] = 0.f;

    for (int k = tid; k < 1024; k += 128) {
        float w = rowp[k];
        const float4* bm = (const float4*)(B_mat + (size_t)k * 16);
        float4 m0 = bm[0], m1 = bm[1], m2 = bm[2], m3 = bm[3];
        acc[0]  += w * m0.x; acc[1]  += w * m0.y; acc[2]  += w * m0.z; acc[3]  += w * m0.w;
        acc[4]  += w * m1.x; acc[5]  += w * m1.y; acc[6]  += w * m1.z; acc[7]  += w * m1.w;
        acc[8]  += w * m2.x; acc[9]  += w * m2.y; acc[10] += w * m2.z; acc[11] += w * m2.w;
        acc[12] += w * m3.x; acc[13] += w * m3.y; acc[14] += w * m3.z; acc[15] += w * m3.w;
    }
#pragma unroll
    for (int s = 0; s < 16; s++) red[tid][s] = acc[s];
    __syncthreads();
    for (int st = 64; st > 0; st >>= 1) {
        if (tid < st) {
#pragma unroll
            for (int s = 0; s < 16; s++) red[tid][s] += red[tid + st][s];
        }
        __syncthreads();
    }
    if (i < 1024) {
        if (tid < 16)       g_WG[i * 48 + tid] = red[0][tid];
        else if (tid < 32)  g_WG[i * 48 + tid] = W_ig[(size_t)i * 16 + (tid - 16)];
        else if (tid < 48)  g_WG[i * 48 + tid] = W_fg[(size_t)i * 16 + (tid - 32)];
    } else {
        if (tid < 16)       g_gb[tid] = red[0][tid];
        else if (tid < 32)  g_gb[tid] = b_ig[tid - 16];
        else if (tid < 48)  g_gb[tid] = b_fg[tid - 32];
    }
}

// ---------------- big SGEMM: 128x128 tiles, BK=16, 8x8/thread, 2-stage -----
// MODE 0: g_xp = x @ W_in + b_in
// MODE 1: g_y  = tanh(g_xp @ W_D + b_D + g_h @ C_mat)
// MODE 2: out  = g_y @ W_out + b_out + g_xp
template <int MODE>
__global__ void __launch_bounds__(256, 2)
gemm128(const float* __restrict__ Ain, const float* __restrict__ Bw,
        const float* __restrict__ bias, const float* __restrict__ Cm,
        float* __restrict__ Cout)
{
    __shared__ float As[2][16][128];
    __shared__ float Bs[2][16][128];

    const float* A = (MODE == 0) ? Ain : (MODE == 1 ? g_xp : g_y);
    float* C = (MODE == 2) ? Cout : (MODE == 0 ? g_xp : g_y);

    const int tid = threadIdx.x;
    const int tx = tid & 15, ty = tid >> 4;
    const int rowBase = blockIdx.y * 128;
    const int colBase = blockIdx.x * 128;

    // per-thread tile-load coordinates (2 float4 each for A and B)
    const int f0 = tid * 2, f1 = tid * 2 + 1;
    const int aRow0 = f0 >> 2, aK0 = (f0 & 3) << 2;
    const int aRow1 = f1 >> 2, aK1 = (f1 & 3) << 2;
    const int bK0 = f0 >> 5, bN0 = (f0 & 31) << 2;
    const int bK1 = f1 >> 5, bN1 = (f1 & 31) << 2;

    float acc[8][8];
#pragma unroll
    for (int i = 0; i < 8; i++)
#pragma unroll
        for (int j = 0; j < 8; j++) acc[i][j] = 0.f;

    // prologue: load tile k0=0 directly into smem buffer 0
    {
        float4 a0 = *(const float4*)(A + (size_t)(rowBase + aRow0) * KDIM + aK0);
        float4 a1 = *(const float4*)(A + (size_t)(rowBase + aRow1) * KDIM + aK1);
        As[0][aK0 + 0][aRow0] = a0.x; As[0][aK0 + 1][aRow0] = a0.y;
        As[0][aK0 + 2][aRow0] = a0.z; As[0][aK0 + 3][aRow0] = a0.w;
        As[0][aK1 + 0][aRow1] = a1.x; As[0][aK1 + 1][aRow1] = a1.y;
        As[0][aK1 + 2][aRow1] = a1.z; As[0][aK1 + 3][aRow1] = a1.w;
        *(float4*)&Bs[0][bK0][bN0] = *(const float4*)(Bw + (size_t)bK0 * NDIM + colBase + bN0);
        *(float4*)&Bs[0][bK1][bN1] = *(const float4*)(Bw + (size_t)bK1 * NDIM + colBase + bN1);
    }
    __syncthreads();

    int buf = 0;
    for (int k0 = 16; k0 <= KDIM; k0 += 16) {
        float4 pa0, pa1, pb0, pb1;
        const bool more = (k0 < KDIM);
        if (more) {
            pa0 = *(const float4*)(A + (size_t)(rowBase + aRow0) * KDIM + k0 + aK0);
            pa1 = *(const float4*)(A + (size_t)(rowBase + aRow1) * KDIM + k0 + aK1);
            pb0 = *(const float4*)(Bw + (size_t)(k0 + bK0) * NDIM + colBase + bN0);
            pb1 = *(const float4*)(Bw + (size_t)(k0 + bK1) * NDIM + colBase + bN1);
        }
#pragma unroll
        for (int k = 0; k < 16; k++) {
            float ar[8], br[8];
            *(float4*)(ar)     = *(const float4*)&As[buf][k][ty * 8];
            *(float4*)(ar + 4) = *(const float4*)&As[buf][k][ty * 8 + 4];
            *(float4*)(br)     = *(const float4*)&Bs[buf][k][tx * 8];
            *(float4*)(br + 4) = *(const float4*)&Bs[buf][k][tx * 8 + 4];
#pragma unroll
            for (int i = 0; i < 8; i++)
#pragma unroll
                for (int j = 0; j < 8; j++) acc[i][j] += ar[i] * br[j];
        }
        if (more) {
            int nb = buf ^ 1;
            As[nb][aK0 + 0][aRow0] = pa0.x; As[nb][aK0 + 1][aRow0] = pa0.y;
            As[nb][aK0 + 2][aRow0] = pa0.z; As[nb][aK0 + 3][aRow0] = pa0.w;
            As[nb][aK1 + 0][aRow1] = pa1.x; As[nb][aK1 + 1][aRow1] = pa1.y;
            As[nb][aK1 + 2][aRow1] = pa1.z; As[nb][aK1 + 3][aRow1] = pa1.w;
            *(float4*)&Bs[nb][bK0][bN0] = pb0;
            *(float4*)&Bs[nb][bK1][bN1] = pb1;
            buf = nb;
            __syncthreads();
        }
    }

    if (MODE == 1) {
        // K-extension: + g_h[M,16] @ C_mat[16,N]  (one extra 16-deep tile)
        __syncthreads();
        {
            float4 h0 = *(const float4*)(g_h + (size_t)(rowBase + aRow0) * 16 + aK0);
            float4 h1 = *(const float4*)(g_h + (size_t)(rowBase + aRow1) * 16 + aK1);
            As[0][aK0 + 0][aRow0] = h0.x; As[0][aK0 + 1][aRow0] = h0.y;
            As[0][aK0 + 2][aRow0] = h0.z; As[0][aK0 + 3][aRow0] = h0.w;
            As[0][aK1 + 0][aRow1] = h1.x; As[0][aK1 + 1][aRow1] = h1.y;
            As[0][aK1 + 2][aRow1] = h1.z; As[0][aK1 + 3][aRow1] = h1.w;
            *(float4*)&Bs[0][bK0][bN0] = *(const float4*)(Cm + (size_t)bK0 * NDIM + colBase + bN0);
            *(float4*)&Bs[0][bK1][bN1] = *(const float4*)(Cm + (size_t)bK1 * NDIM + colBase + bN1);
        }
        __syncthreads();
#pragma unroll
        for (int k = 0; k < 16; k++) {
            float ar[8], br[8];
            *(float4*)(ar)     = *(const float4*)&As[0][k][ty * 8];
            *(float4*)(ar + 4) = *(const float4*)&As[0][k][ty * 8 + 4];
            *(float4*)(br)     = *(const float4*)&Bs[0][k][tx * 8];
            *(float4*)(br + 4) = *(const float4*)&Bs[0][k][tx * 8 + 4];
#pragma unroll
            for (int i = 0; i < 8; i++)
#pragma unroll
                for (int j = 0; j < 8; j++) acc[i][j] += ar[i] * br[j];
        }
    }

    // epilogue
    float bcol[8];
    *(float4*)(bcol)     = *(const float4*)(bias + colBase + tx * 8);
    *(float4*)(bcol + 4) = *(const float4*)(bias + colBase + tx * 8 + 4);
#pragma unroll
    for (int i = 0; i < 8; i++) {
        int row = rowBase + ty * 8 + i;
        size_t base = (size_t)row * NDIM + colBase + tx * 8;
        float out[8];
        if (MODE == 2) {
            float4 r0 = *(const float4*)(g_xp + base);
            float4 r1 = *(const float4*)(g_xp + base + 4);
            out[0] = r0.x; out[1] = r0.y; out[2] = r0.z; out[3] = r0.w;
            out[4] = r1.x; out[5] = r1.y; out[6] = r1.z; out[7] = r1.w;
        } else {
#pragma unroll
            for (int j = 0; j < 8; j++) out[j] = 0.f;
        }
#pragma unroll
        for (int j = 0; j < 8; j++) {
            float v = acc[i][j] + bcol[j] + out[j];
            if (MODE == 1) v = tanhf(v);
            out[j] = v;
        }
        *(float4*)(C + base)     = make_float4(out[0], out[1], out[2], out[3]);
        *(float4*)(C + base + 4) = make_float4(out[4], out[5], out[6], out[7]);
    }
}

// ---------------- gates: [Bx|ig|fg] = g_xp @ g_WG + g_gb; emit a_t, b_t -----
__global__ void __launch_bounds__(256)
gates_kernel()
{
    __shared__ float As[16][128];
    __shared__ float Ws[16][48];
    const int tid = threadIdx.x;
    const int tx = tid & 15, ty = tid >> 4;     // tx = state s, ty*8.. = rows
    const int rowBase = blockIdx.x * 128;

    float acc[8][3];
#pragma unroll
    for (int i = 0; i < 8; i++) { acc[i][0] = 0.f; acc[i][1] = 0.f; acc[i][2] = 0.f; }

    for (int k0 = 0; k0 < KDIM; k0 += 16) {
#pragma unroll
        for (int i = 0; i < 2; i++) {
            int f = tid * 2 + i;
            int aRow = f >> 2, aK = (f & 3) << 2;
            float4 av = *(const float4*)(g_xp + (size_t)(rowBase + aRow) * KDIM + k0 + aK);
            As[aK + 0][aRow] = av.x; As[aK + 1][aRow] = av.y;
            As[aK + 2][aRow] = av.z; As[aK + 3][aRow] = av.w;
        }
        if (tid < 192) {
            int wK = tid / 12, wN = (tid % 12) * 4;
            *(float4*)&Ws[wK][wN] = *(const float4*)(g_WG + (size_t)(k0 + wK) * 48 + wN);
        }
        __syncthreads();
#pragma unroll
        for (int k = 0; k < 16; k++) {
            float ar[8];
            *(float4*)(ar)     = *(const float4*)&As[k][ty * 8];
            *(float4*)(ar + 4) = *(const float4*)&As[k][ty * 8 + 4];
            float wB = Ws[k][tx], wI = Ws[k][tx + 16], wF = Ws[k][tx + 32];
#pragma unroll
            for (int i = 0; i < 8; i++) {
                acc[i][0] += ar[i] * wB;
                acc[i][1] += ar[i] * wI;
                acc[i][2] += ar[i] * wF;
            }
        }
        __syncthreads();
    }

    const int s = tx;
    const float bB = g_gb[s], bI = g_gb[16 + s], bF = g_gb[32 + s];
    const int b = rowBase >> 12;          // T = 4096, 128 | 4096 so b fixed per block
    const int tBase = rowBase & 4095;
#pragma unroll
    for (int i = 0; i < 8; i++) {
        int t = tBase + ty * 8 + i;
        float Bx = acc[i][0] + bB;
        float ig = 1.f / (1.f + expf(-(acc[i][1] + bI)));
        float fg = 1.f / (1.f + expf(-(acc[i][2] + bF)));
        size_t idx = (size_t)(b * 16 + s) * TSZ + t;
        g_a[idx]  = fg;
        g_bq[idx] = ig * Bx;
    }
}

// ---------------- linear-recurrence scan: 128 chains of T=4096 -------------
__global__ void __launch_bounds__(256)
scan_kernel()
{
    __shared__ float sA[256];
    __shared__ float sB[256];
    const int tid = threadIdx.x;
    const int chain = blockIdx.x;           // b*16 + s
    const int b = chain >> 4, s = chain & 15;
    const size_t base = (size_t)chain * TSZ;

    float la[16], lb[16];
#pragma unroll
    for (int j = 0; j < 4; j++) {
        *(float4*)(la + j * 4) = *(const float4*)(g_a  + base + tid * 16 + j * 4);
        *(float4*)(lb + j * 4) = *(const float4*)(g_bq + base + tid * 16 + j * 4);
    }

    // local composition across 16 steps: h_out = A*h_in + Bc
    float Aagg = 1.f, Bc = 0.f;
#pragma unroll
    for (int j = 0; j < 16; j++) {
        Bc = la[j] * Bc + lb[j];
        Aagg *= la[j];
    }
    sA[tid] = Aagg; sB[tid] = Bc;
    __syncthreads();

    // inclusive Hillis-Steele scan (composition: (prev-left) then (current))
#pragma unroll
    for (int off = 1; off < 256; off <<= 1) {
        float myA = sA[tid], myB = sB[tid];
        float aL = 1.f, bL = 0.f;
        if (tid >= off) { aL = sA[tid - off]; bL = sB[tid - off]; }
        __syncthreads();
        if (tid >= off) {
            sA[tid] = aL * myA;
            sB[tid] = myA * bL + myB;
        }
        __syncthreads();
    }

    // h0 = 0 -> entering state for this chunk = exclusive-prefix B
    float h = (tid == 0) ? 0.f : sB[tid - 1];

#pragma unroll
    for (int j = 0; j < 16; j++) {
        h = la[j] * h + lb[j];
        int t = tid * 16 + j;
        g_h[((size_t)(b * TSZ + t)) * SSZ + s] = h;
    }
}

// ---------------- LayerNorm (in-place on out) ------------------------------
__global__ void __launch_bounds__(256)
ln_kernel(float* __restrict__ z, const float* __restrict__ gamma,
          const float* __restrict__ beta)
{
    __shared__ float ws[8], wss[8];
    __shared__ float mv[2];
    const int row = blockIdx.x;
    const int tid = threadIdx.x;

    float4 v = *(const float4*)(z + (size_t)row * NDIM + tid * 4);
    float sum = v.x + v.y + v.z + v.w;
    float ss  = v.x * v.x + v.y * v.y + v.z * v.z + v.w * v.w;
#pragma unroll
    for (int o = 16; o > 0; o >>= 1) {
        sum += __shfl_down_sync(0xffffffffu, sum, o);
        ss  += __shfl_down_sync(0xffffffffu, ss, o);
    }
    if ((tid & 31) == 0) { ws[tid >> 5] = sum; wss[tid >> 5] = ss; }
    __syncthreads();
    if (tid == 0) {
        float S = 0.f, SS = 0.f;
#pragma unroll
        for (int q = 0; q < 8; q++) { S += ws[q]; SS += wss[q]; }
        float mu = S * (1.f / 1024.f);
        float var = SS * (1.f / 1024.f) - mu * mu;
        mv[0] = mu;
        mv[1] = rsqrtf(var + 1e-5f);
    }
    __syncthreads();
    float mu = mv[0], r = mv[1];
    float4 g  = *(const float4*)(gamma + tid * 4);
    float4 bb = *(const float4*)(beta + tid * 4);
    float4 o;
    o.x = (v.x - mu) * r * g.x + bb.x;
    o.y = (v.y - mu) * r * g.y + bb.y;
    o.z = (v.z - mu) * r * g.z + bb.z;
    o.w = (v.w - mu) * r * g.w + bb.w;
    *(float4*)(z + (size_t)row * NDIM + tid * 4) = o;
}

// ---------------- launch ---------------------------------------------------
extern "C" void kernel_launch(void* const* d_in, const int* in_sizes, int n_in,
                              void* d_out, int out_size)
{
    const float* x     = (const float*)d_in[0];
    const float* W_in  = (const float*)d_in[1];
    const float* b_in  = (const float*)d_in[2];
    const float* B_mat = (const float*)d_in[3];
    const float* C_mat = (const float*)d_in[4];
    const float* W_B   = (const float*)d_in[5];
    const float* b_B   = (const float*)d_in[6];
    const float* W_D   = (const float*)d_in[7];
    const float* b_D   = (const float*)d_in[8];
    const float* W_out = (const float*)d_in[9];
    const float* b_out = (const float*)d_in[10];
    const float* W_ig  = (const float*)d_in[11];
    const float* b_ig  = (const float*)d_in[12];
    const float* W_fg  = (const float*)d_in[13];
    const float* b_fg  = (const float*)d_in[14];
    const float* gamma = (const float*)d_in[15];
    const float* beta  = (const float*)d_in[16];
    float* out = (float*)d_out;

    // 1. fold W_B@B_mat and pack gate weights/biases
    fold_kernel<<<1025, 128>>>(W_B, B_mat, b_B, W_ig, b_ig, W_fg, b_fg);

    dim3 ggrid(NDIM / 128, MDIM / 128);   // (8, 256)
    // 2. xp = x @ W_in + b_in
    gemm128<0><<<ggrid, 256>>>(x, W_in, b_in, nullptr, nullptr);
    // 3. gates -> a = sigmoid(fg), bq = sigmoid(ig)*Bx   (chain-major layout)
    gates_kernel<<<MDIM / 128, 256>>>();
    // 4. parallel scan of h_t = a_t h_{t-1} + b_t over T per (b,s) chain
    scan_kernel<<<BSZ * SSZ, 256>>>();
    // 5. y = tanh(xp @ W_D + b_D + hs @ C_mat)
    gemm128<1><<<ggrid, 256>>>(nullptr, W_D, b_D, C_mat, nullptr);
    // 6. z = y @ W_out + b_out + xp   -> d_out
    gemm128<2><<<ggrid, 256>>>(nullptr, W_out, b_out, nullptr, out);
    // 7. LayerNorm in-place on d_out
    ln_kernel<<<MDIM, 256>>>(out, gamma, beta);
}

// round 7
// speedup vs baseline: 2.5180x; 2.5180x over previous
#include <cuda_runtime.h>
#include <cuda_bf16.h>
#include <math.h>
#include <stdint.h>

#define MDIM 32768
#define NDIM 1024
#define KDIM 1024
#define BSZ  8
#define TSZ  4096
#define SSZ  16

// ---------------- scratch (device globals) ---------------------------------
// g_xh/g_xl hold x(hi/lo) for tgemm<0>, then are REUSED for y(hi/lo):
// tgemm<1> writes y into them (x split is dead by then), tgemm<2> reads them.
__device__ float g_xp[(size_t)MDIM * NDIM];
__device__ __align__(16) __nv_bfloat16 g_xh [(size_t)MDIM * NDIM];
__device__ __align__(16) __nv_bfloat16 g_xl [(size_t)MDIM * NDIM];
__device__ __align__(16) __nv_bfloat16 g_xph[(size_t)MDIM * NDIM];
__device__ __align__(16) __nv_bfloat16 g_xpl[(size_t)MDIM * NDIM];
__device__ __align__(16) __nv_bfloat16 g_wth[3ull * 1024 * 1024];  // [N,K] hi
__device__ __align__(16) __nv_bfloat16 g_wtl[3ull * 1024 * 1024];  // [N,K] lo
__device__ __align__(16) __nv_bfloat16 g_cth[1024 * 16];           // C^T [N,16] hi
__device__ __align__(16) __nv_bfloat16 g_ctl[1024 * 16];
__device__ __align__(16) __nv_bfloat16 g_hh [(size_t)MDIM * 16];   // hs [M,16] hi
__device__ __align__(16) __nv_bfloat16 g_hl [(size_t)MDIM * 16];
__device__ float g_WG[1024 * 48];
__device__ float g_gb[48];
__device__ float g_a [BSZ * SSZ * TSZ];
__device__ float g_bq[BSZ * SSZ * TSZ];

// ---------------- helpers ---------------------------------------------------
__device__ __forceinline__ uint32_t smem_u32(const void* p) {
    uint32_t a;
    asm("{ .reg .u64 t; cvta.to.shared.u64 t, %1; cvt.u32.u64 %0, t; }"
        : "=r"(a) : "l"(p));
    return a;
}
__device__ __forceinline__ void ldsm4(uint32_t* r, uint32_t addr) {
    asm volatile("ldmatrix.sync.aligned.m8n8.x4.shared.b16 {%0,%1,%2,%3}, [%4];"
        : "=r"(r[0]), "=r"(r[1]), "=r"(r[2]), "=r"(r[3]) : "r"(addr));
}
__device__ __forceinline__ void mma16816(float* c, const uint32_t* a, const uint32_t* b) {
    asm volatile(
        "mma.sync.aligned.m16n8k16.row.col.f32.bf16.bf16.f32 "
        "{%0,%1,%2,%3}, {%4,%5,%6,%7}, {%8,%9}, {%0,%1,%2,%3};"
        : "+f"(c[0]), "+f"(c[1]), "+f"(c[2]), "+f"(c[3])
        : "r"(a[0]), "r"(a[1]), "r"(a[2]), "r"(a[3]), "r"(b[0]), "r"(b[1]));
}

// ---------------- fold: WBB = W_B @ B_mat + gate packing -------------------
__global__ void fold_kernel(const float* __restrict__ W_B,
                            const float* __restrict__ B_mat,
                            const float* __restrict__ b_B,
                            const float* __restrict__ W_ig,
                            const float* __restrict__ b_ig,
                            const float* __restrict__ W_fg,
                            const float* __restrict__ b_fg)
{
    __shared__ float red[128][17];
    const int tid = threadIdx.x;
    const int i = blockIdx.x;
    const float* rowp = (i < 1024) ? (W_B + (size_t)i * 1024) : b_B;

    float acc[16];
#pragma unroll
    for (int s = 0; s < 16; s++) acc[s] = 0.f;
    for (int k = tid; k < 1024; k += 128) {
        float w = rowp[k];
        const float4* bm = (const float4*)(B_mat + (size_t)k * 16);
        float4 m0 = bm[0], m1 = bm[1], m2 = bm[2], m3 = bm[3];
        acc[0]  += w * m0.x; acc[1]  += w * m0.y; acc[2]  += w * m0.z; acc[3]  += w * m0.w;
        acc[4]  += w * m1.x; acc[5]  += w * m1.y; acc[6]  += w * m1.z; acc[7]  += w * m1.w;
        acc[8]  += w * m2.x; acc[9]  += w * m2.y; acc[10] += w * m2.z; acc[11] += w * m2.w;
        acc[12] += w * m3.x; acc[13] += w * m3.y; acc[14] += w * m3.z; acc[15] += w * m3.w;
    }
#pragma unroll
    for (int s = 0; s < 16; s++) red[tid][s] = acc[s];
    __syncthreads();
    for (int st = 64; st > 0; st >>= 1) {
        if (tid < st) {
#pragma unroll
            for (int s = 0; s < 16; s++) red[tid][s] += red[tid + st][s];
        }
        __syncthreads();
    }
    if (i < 1024) {
        if (tid < 16)       g_WG[i * 48 + tid] = red[0][tid];
        else if (tid < 32)  g_WG[i * 48 + tid] = W_ig[(size_t)i * 16 + (tid - 16)];
        else if (tid < 48)  g_WG[i * 48 + tid] = W_fg[(size_t)i * 16 + (tid - 32)];
    } else {
        if (tid < 16)       g_gb[tid] = red[0][tid];
        else if (tid < 32)  g_gb[tid] = b_ig[tid - 16];
        else if (tid < 48)  g_gb[tid] = b_fg[tid - 32];
    }
}

// ---------------- conversions ----------------------------------------------
__device__ __forceinline__ void split_store(__nv_bfloat16* dh, __nv_bfloat16* dl,
                                            size_t off, float v) {
    __nv_bfloat16 h = __float2bfloat16(v);
    dh[off] = h;
    dl[off] = __float2bfloat16(v - __bfloat162float(h));
}

__global__ void convx_kernel(const float* __restrict__ x) {
    size_t i = ((size_t)blockIdx.x * 256 + threadIdx.x) * 4;
    float4 v = *(const float4*)(x + i);
    __nv_bfloat16 h0 = __float2bfloat16(v.x), h1 = __float2bfloat16(v.y);
    __nv_bfloat16 h2 = __float2bfloat16(v.z), h3 = __float2bfloat16(v.w);
    __nv_bfloat162 H01; H01.x = h0; H01.y = h1;
    __nv_bfloat162 H23; H23.x = h2; H23.y = h3;
    ((__nv_bfloat162*)(g_xh + i))[0] = H01;
    ((__nv_bfloat162*)(g_xh + i))[1] = H23;
    __nv_bfloat162 L01, L23;
    L01.x = __float2bfloat16(v.x - __bfloat162float(h0));
    L01.y = __float2bfloat16(v.y - __bfloat162float(h1));
    L23.x = __float2bfloat16(v.z - __bfloat162float(h2));
    L23.y = __float2bfloat16(v.w - __bfloat162float(h3));
    ((__nv_bfloat162*)(g_xl + i))[0] = L01;
    ((__nv_bfloat162*)(g_xl + i))[1] = L23;
}

// transpose+convert weights: W[k][n] -> Wt[n][k] (hi/lo bf16)
__global__ void convw_kernel(const float* __restrict__ W_in,
                             const float* __restrict__ W_D,
                             const float* __restrict__ W_out) {
    __shared__ float t[32][33];
    const int z = blockIdx.z;
    const float* W = (z == 0) ? W_in : ((z == 1) ? W_D : W_out);
    __nv_bfloat16* dh = g_wth + (size_t)z * 1024 * 1024;
    __nv_bfloat16* dl = g_wtl + (size_t)z * 1024 * 1024;
    const int c = threadIdx.x & 31, r0 = threadIdx.x >> 5;
    const int nb = blockIdx.x * 32, kb = blockIdx.y * 32;
#pragma unroll
    for (int i = 0; i < 4; i++) {
        int r = r0 + i * 8;
        t[r][c] = W[(size_t)(kb + r) * 1024 + nb + c];
    }
    __syncthreads();
#pragma unroll
    for (int i = 0; i < 4; i++) {
        int r = r0 + i * 8;
        float v = t[c][r];
        split_store(dh, dl, (size_t)(nb + r) * 1024 + kb + c, v);
    }
}

// C_mat [16,1024] -> Ct [1024,16] hi/lo
__global__ void convc_kernel(const float* __restrict__ C) {
    int n = blockIdx.x * 256 + threadIdx.x;
#pragma unroll
    for (int j = 0; j < 16; j++)
        split_store(g_cth, g_ctl, (size_t)n * 16 + j, C[(size_t)j * 1024 + n]);
}

// ---------------- mma.sync split-bf16 GEMM ---------------------------------
// CTA 128x128, 8 warps (warp tile 32x64), K-chunks of 64 in smem.
// MODE 0: g_xp(+hi/lo->g_xph/g_xpl) = x @ W_in + b_in        (A = g_xh/g_xl)
// MODE 1: y(hi/lo->g_xh/g_xl)       = tanh(xp @ W_D + h @ C_mat + b_D)
// MODE 2: out                       = y @ W_out + b_out + xp (A = g_xh/g_xl)
#define TSTRIDE 72
#define TILE_B  (128 * TSTRIDE * 2)     // 18432
#define SA_H 0
#define SA_L TILE_B
#define SB_H (2 * TILE_B)
#define SB_L (3 * TILE_B)
#define SMEM_TOTAL (4 * TILE_B)         // 73728

template <int MODE>
__global__ void __launch_bounds__(256, 2)
tgemm(const float* __restrict__ bias, float* __restrict__ outp)
{
    extern __shared__ char smem[];
    const uint32_t sb = smem_u32(smem);
    const int tid = threadIdx.x;
    const int lane = tid & 31, wid = tid >> 5;
    const int rowBase = blockIdx.y * 128;
    const int colBase = blockIdx.x * 128;
    const int wm = (wid & 3) * 32;      // warp M offset in CTA tile
    const int wn = (wid >> 2) * 64;     // warp N offset

    const __nv_bfloat16* Ah = (MODE == 1) ? g_xph : g_xh;
    const __nv_bfloat16* Al = (MODE == 1) ? g_xpl : g_xl;
    const __nv_bfloat16* Bh = g_wth + (size_t)MODE * 1024 * 1024;
    const __nv_bfloat16* Bl = g_wtl + (size_t)MODE * 1024 * 1024;

    // ldmatrix per-lane coords
    const int a_r = (lane & 7) + ((lane >> 3) & 1) * 8;   // + wm + mt*16
    const int a_c = (lane >> 4) * 8;                      // + k1
    const int b_r = (lane & 7) + (lane >> 4) * 8;         // + wn + p*16
    const int b_c = ((lane >> 3) & 1) * 8;                // + k1

    // fill coords: 32 rows per pass, 8 uint4 per row
    const int fr = tid >> 3;
    const int fc = (tid & 7) * 8;

    float acc[2][8][4];
#pragma unroll
    for (int mt = 0; mt < 2; mt++)
#pragma unroll
        for (int nt = 0; nt < 8; nt++)
#pragma unroll
            for (int j = 0; j < 4; j++) acc[mt][nt][j] = 0.f;

    for (int chunk = 0; chunk < 16; chunk++) {
        const int k0 = chunk * 64;
#pragma unroll
        for (int i = 0; i < 4; i++) {
            int r = fr + i * 32;
            uint32_t so = (uint32_t)(r * TSTRIDE + fc) * 2;
            size_t ga = (size_t)(rowBase + r) * KDIM + k0 + fc;
            size_t gb = (size_t)(colBase + r) * KDIM + k0 + fc;
            *(uint4*)(smem + SA_H + so) = *(const uint4*)(Ah + ga);
            *(uint4*)(smem + SA_L + so) = *(const uint4*)(Al + ga);
            *(uint4*)(smem + SB_H + so) = *(const uint4*)(Bh + gb);
            *(uint4*)(smem + SB_L + so) = *(const uint4*)(Bl + gb);
        }
        __syncthreads();
#pragma unroll
        for (int k1 = 0; k1 < 64; k1 += 16) {
            uint32_t ah[2][4], al[2][4];
#pragma unroll
            for (int mt = 0; mt < 2; mt++) {
                uint32_t off = (uint32_t)((wm + mt * 16 + a_r) * TSTRIDE + k1 + a_c) * 2;
                ldsm4(ah[mt], sb + SA_H + off);
                ldsm4(al[mt], sb + SA_L + off);
            }
#pragma unroll
            for (int p = 0; p < 4; p++) {
                uint32_t bh[4], bl[4];
                uint32_t off = (uint32_t)((wn + p * 16 + b_r) * TSTRIDE + k1 + b_c) * 2;
                ldsm4(bh, sb + SB_H + off);
                ldsm4(bl, sb + SB_L + off);
#pragma unroll
                for (int mt = 0; mt < 2; mt++) {
#pragma unroll
                    for (int q = 0; q < 2; q++) {
                        float* c = acc[mt][p * 2 + q];
                        mma16816(c, ah[mt], bh + q * 2);
                        mma16816(c, ah[mt], bl + q * 2);
                        mma16816(c, al[mt], bh + q * 2);
                    }
                }
            }
        }
        __syncthreads();
    }

    if (MODE == 1) {
        // K-extension: + h[M,16] @ C^T[N,16]  (one k-step)
        {
            int r = tid >> 1;
            int c = (tid & 1) * 8;
            uint32_t so = (uint32_t)(r * TSTRIDE + c) * 2;
            size_t ga = (size_t)(rowBase + r) * 16 + c;
            size_t gb = (size_t)(colBase + r) * 16 + c;
            *(uint4*)(smem + SA_H + so) = *(const uint4*)(g_hh + ga);
            *(uint4*)(smem + SA_L + so) = *(const uint4*)(g_hl + ga);
            *(uint4*)(smem + SB_H + so) = *(const uint4*)(g_cth + gb);
            *(uint4*)(smem + SB_L + so) = *(const uint4*)(g_ctl + gb);
        }
        __syncthreads();
        {
            uint32_t ah[2][4], al[2][4];
#pragma unroll
            for (int mt = 0; mt < 2; mt++) {
                uint32_t off = (uint32_t)((wm + mt * 16 + a_r) * TSTRIDE + a_c) * 2;
                ldsm4(ah[mt], sb + SA_H + off);
                ldsm4(al[mt], sb + SA_L + off);
            }
#pragma unroll
            for (int p = 0; p < 4; p++) {
                uint32_t bh[4], bl[4];
                uint32_t off = (uint32_t)((wn + p * 16 + b_r) * TSTRIDE + b_c) * 2;
                ldsm4(bh, sb + SB_H + off);
                ldsm4(bl, sb + SB_L + off);
#pragma unroll
                for (int mt = 0; mt < 2; mt++) {
#pragma unroll
                    for (int q = 0; q < 2; q++) {
                        float* c = acc[mt][p * 2 + q];
                        mma16816(c, ah[mt], bh + q * 2);
                        mma16816(c, ah[mt], bl + q * 2);
                        mma16816(c, al[mt], bh + q * 2);
                    }
                }
            }
        }
    }

    // epilogue
    const int lr = lane >> 2, lc = (lane & 3) * 2;
#pragma unroll
    for (int mt = 0; mt < 2; mt++) {
        const int row0 = rowBase + wm + mt * 16 + lr;
#pragma unroll
        for (int nt = 0; nt < 8; nt++) {
            const int col = colBase + wn + nt * 8 + lc;
            const float2 bb = *(const float2*)(bias + col);
#pragma unroll
            for (int h = 0; h < 2; h++) {
                const int row = row0 + h * 8;
                const size_t off = (size_t)row * NDIM + col;
                float v0 = acc[mt][nt][h * 2 + 0] + bb.x;
                float v1 = acc[mt][nt][h * 2 + 1] + bb.y;
                if (MODE == 1) { v0 = tanhf(v0); v1 = tanhf(v1); }
                if (MODE == 2) {
                    float2 xp2 = *(const float2*)(g_xp + off);
                    v0 += xp2.x; v1 += xp2.y;
                    *(float2*)(outp + off) = make_float2(v0, v1);
                }
                if (MODE == 0) {
                    *(float2*)(g_xp + off) = make_float2(v0, v1);
                }
                if (MODE == 0 || MODE == 1) {
                    __nv_bfloat16* dh = (MODE == 0) ? g_xph : g_xh;  // MODE1: y -> reuse x bufs
                    __nv_bfloat16* dl = (MODE == 0) ? g_xpl : g_xl;
                    __nv_bfloat16 h0 = __float2bfloat16(v0);
                    __nv_bfloat16 h1 = __float2bfloat16(v1);
                    __nv_bfloat162 H; H.x = h0; H.y = h1;
                    *(__nv_bfloat162*)(dh + off) = H;
                    __nv_bfloat162 L;
                    L.x = __float2bfloat16(v0 - __bfloat162float(h0));
                    L.y = __float2bfloat16(v1 - __bfloat162float(h1));
                    *(__nv_bfloat162*)(dl + off) = L;
                }
            }
        }
    }
}

// ---------------- gates: [Bx|ig|fg] = g_xp @ g_WG + g_gb -------------------
__global__ void __launch_bounds__(256)
gates_kernel()
{
    __shared__ float As[16][128];
    __shared__ float Ws[16][48];
    const int tid = threadIdx.x;
    const int tx = tid & 15, ty = tid >> 4;
    const int rowBase = blockIdx.x * 128;

    float acc[8][3];
#pragma unroll
    for (int i = 0; i < 8; i++) { acc[i][0] = 0.f; acc[i][1] = 0.f; acc[i][2] = 0.f; }

    for (int k0 = 0; k0 < KDIM; k0 += 16) {
#pragma unroll
        for (int i = 0; i < 2; i++) {
            int f = tid * 2 + i;
            int aRow = f >> 2, aK = (f & 3) << 2;
            float4 av = *(const float4*)(g_xp + (size_t)(rowBase + aRow) * KDIM + k0 + aK);
            As[aK + 0][aRow] = av.x; As[aK + 1][aRow] = av.y;
            As[aK + 2][aRow] = av.z; As[aK + 3][aRow] = av.w;
        }
        if (tid < 192) {
            int wK = tid / 12, wN = (tid % 12) * 4;
            *(float4*)&Ws[wK][wN] = *(const float4*)(g_WG + (size_t)(k0 + wK) * 48 + wN);
        }
        __syncthreads();
#pragma unroll
        for (int k = 0; k < 16; k++) {
            float ar[8];
            *(float4*)(ar)     = *(const float4*)&As[k][ty * 8];
            *(float4*)(ar + 4) = *(const float4*)&As[k][ty * 8 + 4];
            float wB = Ws[k][tx], wI = Ws[k][tx + 16], wF = Ws[k][tx + 32];
#pragma unroll
            for (int i = 0; i < 8; i++) {
                acc[i][0] += ar[i] * wB;
                acc[i][1] += ar[i] * wI;
                acc[i][2] += ar[i] * wF;
            }
        }
        __syncthreads();
    }

    const int s = tx;
    const float bB = g_gb[s], bI = g_gb[16 + s], bF = g_gb[32 + s];
    const int b = rowBase >> 12;
    const int tBase = rowBase & 4095;
#pragma unroll
    for (int i = 0; i < 8; i++) {
        int t = tBase + ty * 8 + i;
        float Bx = acc[i][0] + bB;
        float ig = 1.f / (1.f + expf(-(acc[i][1] + bI)));
        float fg = 1.f / (1.f + expf(-(acc[i][2] + bF)));
        size_t idx = (size_t)(b * 16 + s) * TSZ + t;
        g_a[idx]  = fg;
        g_bq[idx] = ig * Bx;
    }
}

// ---------------- parallel scan; writes h as bf16 hi/lo --------------------
__global__ void __launch_bounds__(256)
scan_kernel()
{
    __shared__ float sA[256];
    __shared__ float sB[256];
    const int tid = threadIdx.x;
    const int chain = blockIdx.x;
    const int b = chain >> 4, s = chain & 15;
    const size_t base = (size_t)chain * TSZ;

    float la[16], lb[16];
#pragma unroll
    for (int j = 0; j < 4; j++) {
        *(float4*)(la + j * 4) = *(const float4*)(g_a  + base + tid * 16 + j * 4);
        *(float4*)(lb + j * 4) = *(const float4*)(g_bq + base + tid * 16 + j * 4);
    }

    float Aagg = 1.f, Bc = 0.f;
#pragma unroll
    for (int j = 0; j < 16; j++) {
        Bc = la[j] * Bc + lb[j];
        Aagg *= la[j];
    }
    sA[tid] = Aagg; sB[tid] = Bc;
    __syncthreads();

#pragma unroll
    for (int off = 1; off < 256; off <<= 1) {
        float myA = sA[tid], myB = sB[tid];
        float aL = 1.f, bL = 0.f;
        if (tid >= off) { aL = sA[tid - off]; bL = sB[tid - off]; }
        __syncthreads();
        if (tid >= off) {
            sA[tid] = aL * myA;
            sB[tid] = myA * bL + myB;
        }
        __syncthreads();
    }

    float h = (tid == 0) ? 0.f : sB[tid - 1];
#pragma unroll
    for (int j = 0; j < 16; j++) {
        h = la[j] * h + lb[j];
        int t = tid * 16 + j;
        size_t off = ((size_t)(b * TSZ + t)) * 16 + s;
        __nv_bfloat16 hh = __float2bfloat16(h);
        g_hh[off] = hh;
        g_hl[off] = __float2bfloat16(h - __bfloat162float(hh));
    }
}

// ---------------- LayerNorm (in-place) -------------------------------------
__global__ void __launch_bounds__(256)
ln_kernel(float* __restrict__ z, const float* __restrict__ gamma,
          const float* __restrict__ beta)
{
    __shared__ float ws[8], wss[8];
    __shared__ float mv[2];
    const int row = blockIdx.x;
    const int tid = threadIdx.x;

    float4 v = *(const float4*)(z + (size_t)row * NDIM + tid * 4);
    float sum = v.x + v.y + v.z + v.w;
    float ss  = v.x * v.x + v.y * v.y + v.z * v.z + v.w * v.w;
#pragma unroll
    for (int o = 16; o > 0; o >>= 1) {
        sum += __shfl_down_sync(0xffffffffu, sum, o);
        ss  += __shfl_down_sync(0xffffffffu, ss, o);
    }
    if ((tid & 31) == 0) { ws[tid >> 5] = sum; wss[tid >> 5] = ss; }
    __syncthreads();
    if (tid == 0) {
        float S = 0.f, SS = 0.f;
#pragma unroll
        for (int q = 0; q < 8; q++) { S += ws[q]; SS += wss[q]; }
        float mu = S * (1.f / 1024.f);
        float var = SS * (1.f / 1024.f) - mu * mu;
        mv[0] = mu;
        mv[1] = rsqrtf(var + 1e-5f);
    }
    __syncthreads();
    float mu = mv[0], r = mv[1];
    float4 g  = *(const float4*)(gamma + tid * 4);
    float4 bb = *(const float4*)(beta + tid * 4);
    float4 o;
    o.x = (v.x - mu) * r * g.x + bb.x;
    o.y = (v.y - mu) * r * g.y + bb.y;
    o.z = (v.z - mu) * r * g.z + bb.z;
    o.w = (v.w - mu) * r * g.w + bb.w;
    *(float4*)(z + (size_t)row * NDIM + tid * 4) = o;
}

// ---------------- launch ---------------------------------------------------
extern "C" void kernel_launch(void* const* d_in, const int* in_sizes, int n_in,
                              void* d_out, int out_size)
{
    const float* x     = (const float*)d_in[0];
    const float* W_in  = (const float*)d_in[1];
    const float* b_in  = (const float*)d_in[2];
    const float* B_mat = (const float*)d_in[3];
    const float* C_mat = (const float*)d_in[4];
    const float* W_B   = (const float*)d_in[5];
    const float* b_B   = (const float*)d_in[6];
    const float* W_D   = (const float*)d_in[7];
    const float* b_D   = (const float*)d_in[8];
    const float* W_out = (const float*)d_in[9];
    const float* b_out = (const float*)d_in[10];
    const float* W_ig  = (const float*)d_in[11];
    const float* b_ig  = (const float*)d_in[12];
    const float* W_fg  = (const float*)d_in[13];
    const float* b_fg  = (const float*)d_in[14];
    const float* gamma = (const float*)d_in[15];
    const float* beta  = (const float*)d_in[16];
    float* out = (float*)d_out;

    cudaFuncSetAttribute(tgemm<0>, cudaFuncAttributeMaxDynamicSharedMemorySize, SMEM_TOTAL);
    cudaFuncSetAttribute(tgemm<1>, cudaFuncAttributeMaxDynamicSharedMemorySize, SMEM_TOTAL);
    cudaFuncSetAttribute(tgemm<2>, cudaFuncAttributeMaxDynamicSharedMemorySize, SMEM_TOTAL);

    fold_kernel<<<1025, 128>>>(W_B, B_mat, b_B, W_ig, b_ig, W_fg, b_fg);
    convx_kernel<<<32768, 256>>>(x);
    convw_kernel<<<dim3(32, 32, 3), 256>>>(W_in, W_D, W_out);
    convc_kernel<<<4, 256>>>(C_mat);

    dim3 tgrid(NDIM / 128, MDIM / 128);   // (8, 256)
    tgemm<0><<<tgrid, 256, SMEM_TOTAL>>>(b_in, nullptr);
    gates_kernel<<<MDIM / 128, 256>>>();
    scan_kernel<<<BSZ * SSZ, 256>>>();
    tgemm<1><<<tgrid, 256, SMEM_TOTAL>>>(b_D, nullptr);
    tgemm<2><<<tgrid, 256, SMEM_TOTAL>>>(b_out, out);
    ln_kernel<<<MDIM, 256>>>(out, gamma, beta);
}